// round 1
// baseline (speedup 1.0000x reference)
#include <cuda_runtime.h>

// Packed fp32x2 FMA (Blackwell FFMA2): d.lo = a.lo*b.lo + d.lo ; d.hi likewise.
#define FMA2(accv, av, bv) \
    asm("fma.rn.f32x2 %0, %1, %2, %0;" : "+l"(accv) : "l"(av), "l"(bv))

struct Params {
    const float* feat[3];
    const void*  pid[3];
    const float* w1[3];
    const float* b1[3];
    const float* w2[3];
    const float* b2[3];
    float* out;
    int C[3];
    int HW[3];
};

constexpr int MT  = 32;    // rows per block tile
constexpr int KT  = 32;    // K chunk
constexpr int NC  = 256;   // hidden/output channels
constexpr int NTH = 256;   // threads per block
constexpr int P   = 256;   // patches per batch

// smem floats: xs 1024 | ws 8192 | hs 8192 | rowbase(32 ll=64 f) | pnorm 64 | flag 16
constexpr int    SMEM_FLOATS = 1024 + 8192 + 8192 + 64 + 64 + 16;
constexpr size_t SMEM_BYTES  = SMEM_FLOATS * sizeof(float);

__global__ __launch_bounds__(NTH, 2)
void patch_mlp_kernel(Params prm) {
    extern __shared__ float smem[];
    float*     xs      = smem;                         // [MT][KT] k-contiguous
    float*     ws      = smem + 1024;                  // [KT/4][NC] float4 k-quads
    float*     hs      = smem + 1024 + 8192;           // [MT][NC]
    long long* rowbase = (long long*)(smem + 1024 + 8192 + 8192);
    float*     pnorm   = smem + 1024 + 8192 + 8192 + 64;
    int*       flag    = (int*)(pnorm + 64);

    const int bx    = blockIdx.x;
    const int stage = bx % 3;
    const int tile  = bx / 3;
    const int m0    = tile * MT;
    const int tid   = threadIdx.x;

    const int        C    = prm.C[stage];
    const long long  HW   = prm.HW[stage];
    const float* __restrict__ feat = prm.feat[stage];

    // --- detect int32 vs int64 patch_id on device (deterministic) ---
    if (tid == 0) *flag = 1;
    __syncthreads();
    if (tid < 128) {
        long long v = ((const long long*)prm.pid[stage])[tid];
        if (v < 0 || v >= HW) *flag = 0;   // benign race: all writers write 0
    }
    __syncthreads();
    const int is64 = *flag;

    if (tid < MT) {
        int m  = m0 + tid;
        int b  = m >> 8;        // row = b*256 + p
        int pp = m & (P - 1);
        long long s = is64 ? ((const long long*)prm.pid[stage])[pp]
                           : (long long)((const int*)prm.pid[stage])[pp];
        rowbase[tid] = (long long)b * C * HW + s;
    }
    __syncthreads();

    const int rowg = tid >> 6;      // 0..3  (constant within a warp)
    const int colg = tid & 63;      // 0..63
    const int r0   = rowg * 8;
    const int lk   = tid & 31;      // gather k lane
    const int lr   = (tid >> 5) * 4;// gather row base

    const float* fb0 = feat + rowbase[lr + 0] + (long long)lk * HW;
    const float* fb1 = feat + rowbase[lr + 1] + (long long)lk * HW;
    const float* fb2 = feat + rowbase[lr + 2] + (long long)lk * HW;
    const float* fb3 = feat + rowbase[lr + 3] + (long long)lk * HW;
    const long long kstep = (long long)KT * HW;

    unsigned long long acc[8][4];
#pragma unroll
    for (int rr = 0; rr < 8; rr++)
#pragma unroll
        for (int jj = 0; jj < 4; jj++) acc[rr][jj] = 0ULL;

    // ---------------- Phase 1: hidden = relu(x @ w1 + b1) ----------------
    {
        const float* __restrict__ w = prm.w1[stage];
        const int nch = C / KT;
        for (int ch = 0; ch < nch; ch++) {
            if (ch) __syncthreads();
            // gather x chunk: lanes write consecutive k -> conflict-free
            xs[(lr + 0) * KT + lk] = __ldg(fb0); fb0 += kstep;
            xs[(lr + 1) * KT + lk] = __ldg(fb1); fb1 += kstep;
            xs[(lr + 2) * KT + lk] = __ldg(fb2); fb2 += kstep;
            xs[(lr + 3) * KT + lk] = __ldg(fb3); fb3 += kstep;
            // repack w1 chunk as k-quads: ws4[kq][t] = {w[4kq..4kq+3][t]}
            const int kb = ch * KT;
#pragma unroll
            for (int kq = 0; kq < 8; kq++) {
                float4 v;
                v.x = w[(kb + kq * 4 + 0) * NC + tid];
                v.y = w[(kb + kq * 4 + 1) * NC + tid];
                v.z = w[(kb + kq * 4 + 2) * NC + tid];
                v.w = w[(kb + kq * 4 + 3) * NC + tid];
                ((float4*)ws)[kq * NC + tid] = v;
            }
            __syncthreads();
#pragma unroll
            for (int kq = 0; kq < 8; kq++) {
                ulonglong2 b4[4];
#pragma unroll
                for (int jj = 0; jj < 4; jj++)
                    b4[jj] = ((const ulonglong2*)ws)[kq * NC + colg + 64 * jj];
#pragma unroll
                for (int rr = 0; rr < 8; rr++) {
                    ulonglong2 a2 = ((const ulonglong2*)xs)[(r0 + rr) * 8 + kq];
#pragma unroll
                    for (int jj = 0; jj < 4; jj++) {
                        FMA2(acc[rr][jj], a2.x, b4[jj].x);
                        FMA2(acc[rr][jj], a2.y, b4[jj].y);
                    }
                }
            }
        }
    }

    // ---- ReLU + bias -> hs ----
    {
        float b1v[4];
#pragma unroll
        for (int jj = 0; jj < 4; jj++) b1v[jj] = prm.b1[stage][colg + 64 * jj];
#pragma unroll
        for (int rr = 0; rr < 8; rr++)
#pragma unroll
            for (int jj = 0; jj < 4; jj++) {
                float2 f = *(float2*)&acc[rr][jj];
                float h = fmaxf(f.x + f.y + b1v[jj], 0.f);
                hs[(r0 + rr) * NC + colg + 64 * jj] = h;
                acc[rr][jj] = 0ULL;
            }
    }
    __syncthreads();

    // ---------------- Phase 2: y = hs @ w2 + b2 ----------------
    {
        const float* __restrict__ w = prm.w2[stage];
        for (int ch = 0; ch < NC / KT; ch++) {
            if (ch) __syncthreads();
            const int kb = ch * KT;
#pragma unroll
            for (int kq = 0; kq < 8; kq++) {
                float4 v;
                v.x = w[(kb + kq * 4 + 0) * NC + tid];
                v.y = w[(kb + kq * 4 + 1) * NC + tid];
                v.z = w[(kb + kq * 4 + 2) * NC + tid];
                v.w = w[(kb + kq * 4 + 3) * NC + tid];
                ((float4*)ws)[kq * NC + tid] = v;
            }
            __syncthreads();
#pragma unroll
            for (int kq = 0; kq < 8; kq++) {
                ulonglong2 b4[4];
#pragma unroll
                for (int jj = 0; jj < 4; jj++)
                    b4[jj] = ((const ulonglong2*)ws)[kq * NC + colg + 64 * jj];
#pragma unroll
                for (int rr = 0; rr < 8; rr++) {
                    ulonglong2 a2 = ((const ulonglong2*)hs)[(r0 + rr) * 64 + ch * 8 + kq];
#pragma unroll
                    for (int jj = 0; jj < 4; jj++) {
                        FMA2(acc[rr][jj], a2.x, b4[jj].x);
                        FMA2(acc[rr][jj], a2.y, b4[jj].y);
                    }
                }
            }
        }
    }

    // ---------------- Epilogue: bias, L2 normalize, store ----------------
    {
        float b2v[4];
#pragma unroll
        for (int jj = 0; jj < 4; jj++) b2v[jj] = prm.b2[stage][colg + 64 * jj];
        float y[8][4];
        float ps[8];
#pragma unroll
        for (int rr = 0; rr < 8; rr++) {
            float s = 0.f;
#pragma unroll
            for (int jj = 0; jj < 4; jj++) {
                float2 f = *(float2*)&acc[rr][jj];
                float v = f.x + f.y + b2v[jj];
                y[rr][jj] = v;
                s += v * v;
            }
            ps[rr] = s;
        }
#pragma unroll
        for (int off = 16; off > 0; off >>= 1)
#pragma unroll
            for (int rr = 0; rr < 8; rr++)
                ps[rr] += __shfl_xor_sync(0xffffffffu, ps[rr], off);

        const int warpid = tid >> 5;  // two warps share a row-group
        if ((tid & 31) == 0) {
#pragma unroll
            for (int rr = 0; rr < 8; rr++) pnorm[warpid * 8 + rr] = ps[rr];
        }
        __syncthreads();
        const int wp = warpid & ~1;
        float* outp = prm.out + (long long)stage * 4096 * NC + (long long)(m0 + r0) * NC;
#pragma unroll
        for (int rr = 0; rr < 8; rr++) {
            float tot   = pnorm[wp * 8 + rr] + pnorm[(wp + 1) * 8 + rr];
            float scale = 1.f / (sqrtf(tot) + 1e-7f);
#pragma unroll
            for (int jj = 0; jj < 4; jj++)
                outp[rr * NC + colg + 64 * jj] = y[rr][jj] * scale;
        }
    }
}

extern "C" void kernel_launch(void* const* d_in, const int* in_sizes, int n_in,
                              void* d_out, int out_size) {
    (void)n_in; (void)out_size;
    int fi[3], pi[3], w1i[3], b1i[3], w2i[3], b2i[3];
    if (in_sizes[1] == 256) {
        // dict insertion order: feat_i, pid_i, w1_i, b1_i, w2_i, b2_i per stage
        for (int s = 0; s < 3; s++) {
            int b = 6 * s;
            fi[s] = b; pi[s] = b + 1; w1i[s] = b + 2;
            b1i[s] = b + 3; w2i[s] = b + 4; b2i[s] = b + 5;
        }
    } else {
        // reference-signature order: feat0..2, pid0..2, then (w1,b1,w2,b2) per stage
        for (int s = 0; s < 3; s++) {
            fi[s] = s; pi[s] = 3 + s;
            int b = 6 + 4 * s;
            w1i[s] = b; b1i[s] = b + 1; w2i[s] = b + 2; b2i[s] = b + 3;
        }
    }

    Params p;
    for (int s = 0; s < 3; s++) {
        p.feat[s] = (const float*)d_in[fi[s]];
        p.pid[s]  = (const void*)d_in[pi[s]];
        p.w1[s]   = (const float*)d_in[w1i[s]];
        p.b1[s]   = (const float*)d_in[b1i[s]];
        p.w2[s]   = (const float*)d_in[w2i[s]];
        p.b2[s]   = (const float*)d_in[b2i[s]];
        p.C[s]    = in_sizes[w1i[s]] / 256;
        p.HW[s]   = in_sizes[fi[s]] / (16 * p.C[s]);
    }
    p.out = (float*)d_out;

    static bool attr_set = false;
    if (!attr_set) {
        cudaFuncSetAttribute(patch_mlp_kernel,
                             cudaFuncAttributeMaxDynamicSharedMemorySize,
                             (int)SMEM_BYTES);
        attr_set = true;
    }

    patch_mlp_kernel<<<384, NTH, SMEM_BYTES>>>(p);
}

// round 5
// speedup vs baseline: 1.3337x; 1.3337x over previous
#include <cuda_runtime.h>
#include <cuda_bf16.h>
#include <cstdint>

// ==========================================================================
// Pre-split bf16 hi/lo weights, row-major [K][256] per plane.
// w1 stage bases {0, 131072, 393216}, lo plane at +K*256.
// w2 stage s: 917504 + s*131072, lo at +65536. Total 1310720 bf16 = 2.5MB.
// ==========================================================================
__device__ __align__(16) __nv_bfloat16 g_wscr[1310720];

// ---------------- PTX helpers (all baseline sm_80+ PTX) ----------------
__device__ __forceinline__ uint32_t s2u(const void* p) {
    return (uint32_t)__cvta_generic_to_shared(p);
}
__device__ __forceinline__ void ldsm4(uint32_t* r, uint32_t a) {
    asm volatile("ldmatrix.sync.aligned.m8n8.x4.shared.b16 {%0,%1,%2,%3}, [%4];"
                 : "=r"(r[0]), "=r"(r[1]), "=r"(r[2]), "=r"(r[3]) : "r"(a));
}
__device__ __forceinline__ void ldsm4t(uint32_t* r, uint32_t a) {
    asm volatile("ldmatrix.sync.aligned.m8n8.x4.trans.shared.b16 {%0,%1,%2,%3}, [%4];"
                 : "=r"(r[0]), "=r"(r[1]), "=r"(r[2]), "=r"(r[3]) : "r"(a));
}
__device__ __forceinline__ void mma_bf16(float* d, const uint32_t* a,
                                         uint32_t b0, uint32_t b1) {
    asm volatile(
        "mma.sync.aligned.m16n8k16.row.col.f32.bf16.bf16.f32 "
        "{%0,%1,%2,%3}, {%4,%5,%6,%7}, {%8,%9}, {%0,%1,%2,%3};"
        : "+f"(d[0]), "+f"(d[1]), "+f"(d[2]), "+f"(d[3])
        : "r"(a[0]), "r"(a[1]), "r"(a[2]), "r"(a[3]), "r"(b0), "r"(b1));
}
__device__ __forceinline__ void cpa16(uint32_t dst, const void* src) {
    asm volatile("cp.async.cg.shared.global [%0], [%1], 16;" :: "r"(dst), "l"(src));
}
#define CPA_COMMIT() asm volatile("cp.async.commit_group;" ::: "memory")
#define CPA_WAIT1()  asm volatile("cp.async.wait_group 1;" ::: "memory")

// ==========================================================================
// Prep: fp32 weights -> bf16 hi/lo planes, row-major.
// ==========================================================================
struct PrepP { const float* w1[3]; const float* w2[3]; };

__global__ void prep_weights(PrepP pp) {
    for (int idx = blockIdx.x * blockDim.x + threadIdx.x; idx < 655360;
         idx += gridDim.x * blockDim.x) {
        int s, j;
        const float* src;
        long long hioff, looff;
        if (idx < 458752) {
            if (idx < 65536)       { s = 0; j = idx;          hioff = 0;      looff = 65536; }
            else if (idx < 196608) { s = 1; j = idx - 65536;  hioff = 131072; looff = 131072 + 131072; }
            else                   { s = 2; j = idx - 196608; hioff = 393216; looff = 393216 + 262144; }
            src = pp.w1[s];
        } else {
            int i = idx - 458752;
            s = i >> 16; j = i & 65535;
            src = pp.w2[s];
            hioff = 917504LL + s * 131072;
            looff = hioff + 65536;
        }
        float v = src[j];
        __nv_bfloat16 hi = __float2bfloat16(v);
        __nv_bfloat16 lo = __float2bfloat16(v - __bfloat162float(hi));
        g_wscr[hioff + j] = hi;
        g_wscr[looff + j] = lo;
    }
}

// ==========================================================================
// Main fused kernel. MT=32 rows/block, KC=32, 8 warps (2M x 4N).
// ==========================================================================
struct MP {
    const float* feat[3];
    const void*  pid[3];
    const float* b1[3];
    const float* b2[3];
    float* out;
    int C[3];
    int HW[3];
};

// smem byte offsets (A rows padded to 80B, B/hidden rows to 528B)
constexpr int OFF_AHI  = 0;           // 32 x 80
constexpr int OFF_ALO  = 2560;        // 32 x 80
constexpr int OFF_B    = 5120;        // 2 bufs x (hi+lo planes) x 32 x 528
constexpr int BPLANE   = 16896;       // 32*528
constexpr int BBUF     = 33792;       // hi+lo
constexpr int OFF_H    = 72704;       // hidden hi/lo planes, 32 x 528 each
constexpr int HPLANE   = 16896;
constexpr int OFF_PN   = 106496;      // float pn[4][32]
constexpr int OFF_FLAG = 107008;
constexpr int SMEM_ALLOC = 107520;

// One K16 x 128-col MMA step for this warp (both splits of A vs hi/lo B).
__device__ __forceinline__ void chunk_mma_k16(
    float acc[8][4], uint32_t aHi, uint32_t aLo, uint32_t bRowHi, int wn) {
    uint32_t ah[4], al[4];
    ldsm4(ah, aHi);
    ldsm4(al, aLo);
#pragma unroll
    for (int pr = 0; pr < 4; pr++) {
        uint32_t bh[4], bl[4];
        uint32_t bcol = (uint32_t)(wn * 64 + pr * 16) * 2;
        ldsm4t(bh, bRowHi + bcol);
        ldsm4t(bl, bRowHi + bcol + BPLANE);
        mma_bf16(acc[pr * 2], ah, bh[0], bh[1]);
        mma_bf16(acc[pr * 2], ah, bl[0], bl[1]);
        mma_bf16(acc[pr * 2], al, bh[0], bh[1]);
        mma_bf16(acc[pr * 2 + 1], ah, bh[2], bh[3]);
        mma_bf16(acc[pr * 2 + 1], ah, bl[2], bl[3]);
        mma_bf16(acc[pr * 2 + 1], al, bh[2], bh[3]);
    }
}

__global__ __launch_bounds__(256, 2) void patch_mlp_mma(MP p) {
    extern __shared__ char sm[];
    const int tid  = threadIdx.x;
    const int lane = tid & 31;
    const int wid  = tid >> 5;
    const int wm   = wid & 1;        // M group (16 rows)
    const int wn   = wid >> 1;       // N group (64 cols)
    const int ti   = lane & 3;
    const int g    = lane >> 2;

    const int s    = blockIdx.x % 3;
    const int tile = blockIdx.x / 3;
    const int m0   = tile * 32;
    const int C    = p.C[s];
    const long long HW = p.HW[s];
    const float* __restrict__ feat = p.feat[s];

    int* flag = (int*)(sm + OFF_FLAG);
    if (tid == 0) *flag = 1;
    __syncthreads();
    if (tid < 128) {
        long long v = ((const long long*)p.pid[s])[tid];
        if (v < 0 || v >= HW) *flag = 0;
    }
    __syncthreads();
    const int is64 = *flag;

    // gather mapping: row = tid&31, ks = tid>>3? no: ks = tid>>5 (0..7)
    const int grow = tid & 31;
    const int ks   = tid >> 5;
    long long rbase;
    {
        int m = m0 + grow, b = m >> 8, pi = m & 255;
        long long sp = is64 ? ((const long long*)p.pid[s])[pi]
                            : (long long)((const int*)p.pid[s])[pi];
        rbase = (long long)b * C * HW + sp;
    }
    const float* gp = feat + rbase + (long long)ks * HW;
    const long long j8 = 8 * HW, kb = 32 * HW;

    float acc[8][4];
#pragma unroll
    for (int i = 0; i < 8; i++)
#pragma unroll
        for (int jj = 0; jj < 4; jj++) acc[i][jj] = 0.f;

    const int nch = C >> 5;
    const long long w1base = (s == 0) ? 0LL : (s == 1) ? 131072LL : 393216LL;
    const long long Koff   = (long long)C << 8;

    // A-frag smem addresses (fixed for GEMM1)
    const uint32_t smb = s2u(sm);
    const uint32_t aHi1 = smb + OFF_AHI + (wm * 16 + (lane & 15)) * 80 + (lane >> 4) * 16;
    const uint32_t aLo1 = aHi1 + (OFF_ALO - OFF_AHI);

    // ---------------- GEMM1 ----------------
    float gv[4];
#pragma unroll
    for (int j = 0; j < 4; j++) gv[j] = __ldg(gp + j * j8);
    {   // B chunk 0 -> buf0
        const __nv_bfloat16* w = g_wscr + w1base;
        uint32_t dst = smb + OFF_B;
#pragma unroll
        for (int i = tid; i < 2048; i += 256) {
            int pl = i >> 10, k = (i >> 5) & 31, cc = i & 31;
            cpa16(dst + pl * BPLANE + k * 528 + cc * 16, w + pl * Koff + k * 256 + cc * 8);
        }
    }
    CPA_COMMIT();

    for (int c = 0; c < nch; c++) {
        if (c + 1 < nch) {
            const __nv_bfloat16* w = g_wscr + w1base + (long long)(c + 1) * 8192;
            uint32_t dst = smb + OFF_B + ((c + 1) & 1) * BBUF;
#pragma unroll
            for (int i = tid; i < 2048; i += 256) {
                int pl = i >> 10, k = (i >> 5) & 31, cc = i & 31;
                cpa16(dst + pl * BPLANE + k * 528 + cc * 16, w + pl * Koff + k * 256 + cc * 8);
            }
        }
        CPA_COMMIT();
        // convert current gather regs -> A smem (single buffer)
#pragma unroll
        for (int j = 0; j < 4; j++) {
            float v = gv[j];
            __nv_bfloat16 hi = __float2bfloat16(v);
            __nv_bfloat16 lo = __float2bfloat16(v - __bfloat162float(hi));
            int o = grow * 80 + (ks + 8 * j) * 2;
            *(__nv_bfloat16*)(sm + OFF_AHI + o) = hi;
            *(__nv_bfloat16*)(sm + OFF_ALO + o) = lo;
        }
        // prefetch next gather chunk
        if (c + 1 < nch) {
            const float* gpc = gp + (long long)(c + 1) * kb;
#pragma unroll
            for (int j = 0; j < 4; j++) gv[j] = __ldg(gpc + j * j8);
        }
        CPA_WAIT1();
        __syncthreads();
        uint32_t bb = smb + OFF_B + (c & 1) * BBUF + (lane & 15) * 528 + (lane >> 4) * 16;
#pragma unroll
        for (int kk = 0; kk < 2; kk++)
            chunk_mma_k16(acc, aHi1 + kk * 32, aLo1 + kk * 32, bb + kk * 16 * 528, wn);
        __syncthreads();
    }

    // ---- start streaming GEMM2 B chunk0 (overlap with epilogue1) ----
    const long long w2base = 917504LL + (long long)s * 131072;
    {
        const __nv_bfloat16* w = g_wscr + w2base;
        uint32_t dst = smb + OFF_B;
#pragma unroll
        for (int i = tid; i < 2048; i += 256) {
            int pl = i >> 10, k = (i >> 5) & 31, cc = i & 31;
            cpa16(dst + pl * BPLANE + k * 528 + cc * 16, w + pl * 65536 + k * 256 + cc * 8);
        }
    }
    CPA_COMMIT();

    // ---------------- epilogue 1: relu + bias -> hidden hi/lo ----------------
    {
        const float* __restrict__ b1 = p.b1[s];
        const int r0 = wm * 16 + g;
#pragma unroll
        for (int nf = 0; nf < 8; nf++) {
            int c0 = wn * 64 + nf * 8 + ti * 2;
            float ba = __ldg(b1 + c0), bbv = __ldg(b1 + c0 + 1);
            float v0 = fmaxf(acc[nf][0] + ba, 0.f);
            float v1 = fmaxf(acc[nf][1] + bbv, 0.f);
            float v2 = fmaxf(acc[nf][2] + ba, 0.f);
            float v3 = fmaxf(acc[nf][3] + bbv, 0.f);
            __nv_bfloat16 h0 = __float2bfloat16(v0), h1 = __float2bfloat16(v1);
            __nv_bfloat16 h2 = __float2bfloat16(v2), h3 = __float2bfloat16(v3);
            __nv_bfloat162 lo01, lo23;
            lo01.x = __float2bfloat16(v0 - __bfloat162float(h0));
            lo01.y = __float2bfloat16(v1 - __bfloat162float(h1));
            lo23.x = __float2bfloat16(v2 - __bfloat162float(h2));
            lo23.y = __float2bfloat16(v3 - __bfloat162float(h3));
            __nv_bfloat162 hi01; hi01.x = h0; hi01.y = h1;
            __nv_bfloat162 hi23; hi23.x = h2; hi23.y = h3;
            *(__nv_bfloat162*)(sm + OFF_H + r0 * 528 + c0 * 2)            = hi01;
            *(__nv_bfloat162*)(sm + OFF_H + (r0 + 8) * 528 + c0 * 2)      = hi23;
            *(__nv_bfloat162*)(sm + OFF_H + HPLANE + r0 * 528 + c0 * 2)       = lo01;
            *(__nv_bfloat162*)(sm + OFF_H + HPLANE + (r0 + 8) * 528 + c0 * 2) = lo23;
#pragma unroll
            for (int jj = 0; jj < 4; jj++) acc[nf][jj] = 0.f;
        }
    }
    __syncthreads();

    // ---------------- GEMM2: K=256, 8 chunks ----------------
    const uint32_t aRow2 = smb + OFF_H + (wm * 16 + (lane & 15)) * 528 + (lane >> 4) * 16;
    for (int c2 = 0; c2 < 8; c2++) {
        if (c2 + 1 < 8) {
            const __nv_bfloat16* w = g_wscr + w2base + (long long)(c2 + 1) * 8192;
            uint32_t dst = smb + OFF_B + ((c2 + 1) & 1) * BBUF;
#pragma unroll
            for (int i = tid; i < 2048; i += 256) {
                int pl = i >> 10, k = (i >> 5) & 31, cc = i & 31;
                cpa16(dst + pl * BPLANE + k * 528 + cc * 16, w + pl * 65536 + k * 256 + cc * 8);
            }
        }
        CPA_COMMIT();
        CPA_WAIT1();
        __syncthreads();
        uint32_t bb = smb + OFF_B + (c2 & 1) * BBUF + (lane & 15) * 528 + (lane >> 4) * 16;
#pragma unroll
        for (int kk = 0; kk < 2; kk++)
            chunk_mma_k16(acc, aRow2 + c2 * 64 + kk * 32, aRow2 + HPLANE + c2 * 64 + kk * 32,
                          bb + kk * 16 * 528, wn);
        __syncthreads();
    }

    // ---------------- epilogue 2: bias, L2 norm, store ----------------
    {
        const float* __restrict__ b2 = p.b2[s];
        float b2a[8], b2b[8];
#pragma unroll
        for (int nf = 0; nf < 8; nf++) {
            int c0 = wn * 64 + nf * 8 + ti * 2;
            b2a[nf] = __ldg(b2 + c0);
            b2b[nf] = __ldg(b2 + c0 + 1);
        }
        float s0 = 0.f, s1 = 0.f;
#pragma unroll
        for (int nf = 0; nf < 8; nf++) {
            float v0 = acc[nf][0] + b2a[nf], v1 = acc[nf][1] + b2b[nf];
            float v2 = acc[nf][2] + b2a[nf], v3 = acc[nf][3] + b2b[nf];
            s0 += v0 * v0 + v1 * v1;
            s1 += v2 * v2 + v3 * v3;
        }
        s0 += __shfl_xor_sync(0xffffffffu, s0, 1);
        s0 += __shfl_xor_sync(0xffffffffu, s0, 2);
        s1 += __shfl_xor_sync(0xffffffffu, s1, 1);
        s1 += __shfl_xor_sync(0xffffffffu, s1, 2);
        float* pn = (float*)(sm + OFF_PN);
        const int r0 = wm * 16 + g;
        if (ti == 0) {
            pn[wn * 32 + r0]     = s0;
            pn[wn * 32 + r0 + 8] = s1;
        }
        __syncthreads();
        float t0 = pn[r0] + pn[32 + r0] + pn[64 + r0] + pn[96 + r0];
        float t1 = pn[r0 + 8] + pn[32 + r0 + 8] + pn[64 + r0 + 8] + pn[96 + r0 + 8];
        float sc0 = 1.f / (sqrtf(t0) + 1e-7f);
        float sc1 = 1.f / (sqrtf(t1) + 1e-7f);
        float* o0 = p.out + ((long long)s * 4096 + m0 + r0) * 256;
        float* o1 = o0 + 8 * 256;
#pragma unroll
        for (int nf = 0; nf < 8; nf++) {
            int c0 = wn * 64 + nf * 8 + ti * 2;
            float2 u0, u1;
            u0.x = (acc[nf][0] + b2a[nf]) * sc0;
            u0.y = (acc[nf][1] + b2b[nf]) * sc0;
            u1.x = (acc[nf][2] + b2a[nf]) * sc1;
            u1.y = (acc[nf][3] + b2b[nf]) * sc1;
            *(float2*)(o0 + c0) = u0;
            *(float2*)(o1 + c0) = u1;
        }
    }
}

// ==========================================================================
extern "C" void kernel_launch(void* const* d_in, const int* in_sizes, int n_in,
                              void* d_out, int out_size) {
    (void)n_in; (void)out_size;
    int fi[3], pi[3], w1i[3], b1i[3], w2i[3], b2i[3];
    if (in_sizes[1] == 256) {
        for (int s = 0; s < 3; s++) {  // dict order: feat,pid,w1,b1,w2,b2 per stage
            int b = 6 * s;
            fi[s] = b; pi[s] = b + 1; w1i[s] = b + 2;
            b1i[s] = b + 3; w2i[s] = b + 4; b2i[s] = b + 5;
        }
    } else {
        for (int s = 0; s < 3; s++) {  // signature order
            fi[s] = s; pi[s] = 3 + s;
            int b = 6 + 4 * s;
            w1i[s] = b; b1i[s] = b + 1; w2i[s] = b + 2; b2i[s] = b + 3;
        }
    }

    PrepP pw;
    MP p;
    for (int s = 0; s < 3; s++) {
        p.feat[s] = (const float*)d_in[fi[s]];
        p.pid[s]  = (const void*)d_in[pi[s]];
        pw.w1[s]  = (const float*)d_in[w1i[s]];
        p.b1[s]   = (const float*)d_in[b1i[s]];
        pw.w2[s]  = (const float*)d_in[w2i[s]];
        p.b2[s]   = (const float*)d_in[b2i[s]];
        p.C[s]    = in_sizes[w1i[s]] / 256;
        p.HW[s]   = in_sizes[fi[s]] / (16 * p.C[s]);
    }
    p.out = (float*)d_out;

    static bool attr_set = false;
    if (!attr_set) {
        cudaFuncSetAttribute(patch_mlp_mma,
                             cudaFuncAttributeMaxDynamicSharedMemorySize,
                             SMEM_ALLOC);
        attr_set = true;
    }

    prep_weights<<<640, 256>>>(pw);
    patch_mlp_mma<<<384, 256, SMEM_ALLOC>>>(p);
}